// round 4
// baseline (speedup 1.0000x reference)
#include <cuda_runtime.h>
#include <cuda_bf16.h>
#include <math.h>
#include <stdint.h>

#define SEQ    512
#define BATCH  64
#define D_IN   1024
#define D_H    1024
#define M_IN   (SEQ * BATCH)      // 32768
#define BH     (BATCH * D_H)      // 65536
#define GRID_P 128                // persistent blocks for recurrence

typedef unsigned long long ull;

// packed f32x2 helpers (FFMA2: only reachable via PTX fma.rn.f32x2)
__device__ __forceinline__ ull pk2(float lo, float hi) {
    ull r;
    asm("mov.b64 %0, {%1, %2};" : "=l"(r) : "r"(__float_as_uint(lo)), "r"(__float_as_uint(hi)));
    return r;
}
__device__ __forceinline__ void upk2(float& lo, float& hi, ull v) {
    uint32_t a, b;
    asm("mov.b64 {%0, %1}, %2;" : "=r"(a), "=r"(b) : "l"(v));
    lo = __uint_as_float(a); hi = __uint_as_float(b);
}
__device__ __forceinline__ ull fma2(ull a, ull b, ull c) {
    ull d;
    asm("fma.rn.f32x2 %0, %1, %2, %3;" : "=l"(d) : "l"(a), "l"(b), "l"(c));
    return d;
}

// ===========================================================================
// Persistent device state
// ===========================================================================
__device__ float g_hbuf[2][BH];          // double-buffered hidden state
__device__ volatile unsigned g_flags[GRID_P];

__global__ void init_h_kernel(const float* __restrict__ h0) {
    int idx = blockIdx.x * blockDim.x + threadIdx.x;
    if (idx < BH) g_hbuf[0][idx] = h0[idx];
    if (idx < GRID_P) g_flags[idx] = 0u;
}

// ===========================================================================
// Input projection: out[m][n] = sum_i x[m][i]*Wih[n][i] + bih[n] + bhh[n]
// M=32768, N=1024, K=1024. BM=BN=128, BK=16, 8x8 thread tile, 256 threads.
// Inner product in packed fma.rn.f32x2 (2 FLOP-pairs per issue slot).
// ===========================================================================
__global__ __launch_bounds__(256, 2) void input_gemm_kernel(
    const float* __restrict__ x, const float* __restrict__ Wih,
    const float* __restrict__ bih, const float* __restrict__ bhh,
    float* __restrict__ out)
{
    __shared__ __align__(16) float As[16][132];
    __shared__ __align__(16) float Bs[16][132];

    const int tid = threadIdx.x;
    const int m0 = blockIdx.y * 128;
    const int n0 = blockIdx.x * 128;
    const int tx = tid & 15;   // -> n
    const int ty = tid >> 4;   // -> m

    ull acc2[8][4];
    #pragma unroll
    for (int i = 0; i < 8; i++)
        #pragma unroll
        for (int j = 0; j < 4; j++) acc2[i][j] = 0ull;

    for (int k0 = 0; k0 < D_IN; k0 += 16) {
        #pragma unroll
        for (int l = 0; l < 2; l++) {
            int f = tid + l * 256;
            int r = f >> 2, c = (f & 3) * 4;
            float4 v = *(const float4*)(x + (size_t)(m0 + r) * D_IN + k0 + c);
            As[c + 0][r] = v.x; As[c + 1][r] = v.y;
            As[c + 2][r] = v.z; As[c + 3][r] = v.w;
        }
        #pragma unroll
        for (int l = 0; l < 2; l++) {
            int f = tid + l * 256;
            int r = f >> 2, c = (f & 3) * 4;
            float4 v = *(const float4*)(Wih + (size_t)(n0 + r) * D_IN + k0 + c);
            Bs[c + 0][r] = v.x; Bs[c + 1][r] = v.y;
            Bs[c + 2][r] = v.z; Bs[c + 3][r] = v.w;
        }
        __syncthreads();
        #pragma unroll
        for (int k = 0; k < 16; k++) {
            float a[8], b[8];
            *(float4*)&a[0] = *(const float4*)&As[k][ty * 8];
            *(float4*)&a[4] = *(const float4*)&As[k][ty * 8 + 4];
            *(float4*)&b[0] = *(const float4*)&Bs[k][tx * 8];
            *(float4*)&b[4] = *(const float4*)&Bs[k][tx * 8 + 4];
            ull b2[4];
            #pragma unroll
            for (int q = 0; q < 4; q++) b2[q] = pk2(b[2 * q], b[2 * q + 1]);
            #pragma unroll
            for (int i = 0; i < 8; i++) {
                ull a2 = pk2(a[i], a[i]);
                #pragma unroll
                for (int q = 0; q < 4; q++)
                    acc2[i][q] = fma2(a2, b2[q], acc2[i][q]);
            }
        }
        __syncthreads();
    }

    // Epilogue: fused bias (b_ih + b_hh), vectorized stores
    #pragma unroll
    for (int i = 0; i < 8; i++) {
        int m = m0 + ty * 8 + i;
        float accf[8];
        #pragma unroll
        for (int q = 0; q < 4; q++) upk2(accf[2 * q], accf[2 * q + 1], acc2[i][q]);
        #pragma unroll
        for (int j = 0; j < 8; j += 4) {
            int n = n0 + tx * 8 + j;
            float4 o;
            o.x = accf[j + 0] + bih[n + 0] + bhh[n + 0];
            o.y = accf[j + 1] + bih[n + 1] + bhh[n + 1];
            o.z = accf[j + 2] + bih[n + 2] + bhh[n + 2];
            o.w = accf[j + 3] + bih[n + 3] + bhh[n + 3];
            *(float4*)(out + (size_t)m * D_H + n) = o;
        }
    }
}

// ===========================================================================
// Persistent recurrence: 512 steps, 128 blocks x 512 threads, fma.rn.f32x2.
// Block bx owns cols j0=bx*8. Thread: b = tid>>3 (batch), kc = tid&7 (K chunk
// of 128). Whh slice cached in smem as packed column-pairs, skew every 128 k.
// ===========================================================================
__global__ __launch_bounds__(512, 1) void rnn_persistent_kernel(
    const float* __restrict__ Whh, float* __restrict__ out, int write_tail)
{
    __shared__ __align__(16) ull Ws2[4096 + 16];

    const int tid = threadIdx.x;
    const int bx  = blockIdx.x;
    const int j0  = bx * 8;

    // One-time Whh slice load: Ws2[k*4 + (k>>7)*2 + jp] = (W[j0+2jp][k], W[j0+2jp+1][k])
    {
        const int k = tid * 2;
        #pragma unroll
        for (int jp = 0; jp < 4; jp++) {
            float2 wa = *(const float2*)(Whh + (size_t)(j0 + 2 * jp) * D_H + k);
            float2 wb = *(const float2*)(Whh + (size_t)(j0 + 2 * jp + 1) * D_H + k);
            Ws2[(size_t)k * 4 + ((k >> 7) << 1) + jp]             = pk2(wa.x, wb.x);
            Ws2[(size_t)(k + 1) * 4 + (((k + 1) >> 7) << 1) + jp] = pk2(wa.y, wb.y);
        }
    }
    __syncthreads();

    const int b  = tid >> 3;         // 0..63
    const int kc = tid & 7;          // 0..7
    const int kbase = kc << 7;       // kc * 128
    const ull* wbase = Ws2 + (kc << 1);   // fold the skew (k>>7 == kc in chunk)

    for (int t = 0; t < SEQ; t++) {
        const float* hrow = g_hbuf[t & 1] + b * D_H + kbase;
        float* hnew = g_hbuf[(t + 1) & 1];

        ull a0 = 0ull, a1 = 0ull, a2 = 0ull, a3 = 0ull;

        #pragma unroll 4
        for (int i = 0; i < 128; i += 8) {
            float hreg[8];
            float4 h0 = __ldcg((const float4*)(hrow + i));
            float4 h1 = __ldcg((const float4*)(hrow + i + 4));
            *(float4*)&hreg[0] = h0;
            *(float4*)&hreg[4] = h1;
            #pragma unroll
            for (int u = 0; u < 8; u++) {
                const ull* wp = wbase + ((size_t)(kbase + i + u) << 2);
                ulonglong2 wA = *(const ulonglong2*)(wp);
                ulonglong2 wB = *(const ulonglong2*)(wp + 2);
                ull hk2 = pk2(hreg[u], hreg[u]);
                a0 = fma2(hk2, wA.x, a0);
                a1 = fma2(hk2, wA.y, a1);
                a2 = fma2(hk2, wB.x, a2);
                a3 = fma2(hk2, wB.y, a3);
            }
        }

        float a[8];
        upk2(a[0], a[1], a0); upk2(a[2], a[3], a1);
        upk2(a[4], a[5], a2); upk2(a[6], a[7], a3);

        #pragma unroll
        for (int j = 0; j < 8; j++) {
            a[j] += __shfl_xor_sync(0xffffffffu, a[j], 1);
            a[j] += __shfl_xor_sync(0xffffffffu, a[j], 2);
            a[j] += __shfl_xor_sync(0xffffffffu, a[j], 4);
        }

        float s;
        switch (kc) {
            case 0: s = a[0]; break; case 1: s = a[1]; break;
            case 2: s = a[2]; break; case 3: s = a[3]; break;
            case 4: s = a[4]; break; case 5: s = a[5]; break;
            case 6: s = a[6]; break; default: s = a[7]; break;
        }

        const int idx = b * D_H + j0 + kc;
        float* op = out + (size_t)t * BH + idx;
        float hv = tanhf(*op + s);
        *op = hv;
        __stcg(hnew + idx, hv);
        if (write_tail && t == SEQ - 1) out[(size_t)SEQ * BH + idx] = hv;

        // distributed grid barrier (per-block flags, 128 parallel pollers)
        if (t < SEQ - 1) {
            __threadfence();
            __syncthreads();
            if (tid == 0) g_flags[bx] = (unsigned)(t + 1);
            if (tid < GRID_P) {
                const unsigned want = (unsigned)(t + 1);
                while (g_flags[tid] < want) { }
            }
            __threadfence();
            __syncthreads();
        }
    }
}

// ===========================================================================
extern "C" void kernel_launch(void* const* d_in, const int* in_sizes, int n_in,
                              void* d_out, int out_size) {
    const float* x   = (const float*)d_in[0];
    const float* h0  = (const float*)d_in[1];
    const float* Wih = (const float*)d_in[2];
    const float* bih = (const float*)d_in[3];
    const float* Whh = (const float*)d_in[4];
    const float* bhh = (const float*)d_in[5];
    float* out = (float*)d_out;

    init_h_kernel<<<(BH + 255) / 256, 256>>>(h0);

    input_gemm_kernel<<<dim3(D_H / 128, M_IN / 128), 256>>>(x, Wih, bih, bhh, out);

    long long total = (long long)SEQ * BH;
    int write_tail = ((long long)out_size >= total + BH) ? 1 : 0;
    rnn_persistent_kernel<<<GRID_P, 512>>>(Whh, out, write_tail);
}

// round 5
// speedup vs baseline: 1.2911x; 1.2911x over previous
#include <cuda_runtime.h>
#include <cuda_bf16.h>
#include <math.h>
#include <stdint.h>

#define SEQ    512
#define BATCH  64
#define D_IN   1024
#define D_H    1024
#define M_IN   (SEQ * BATCH)      // 32768
#define BH     (BATCH * D_H)      // 65536
#define GRID_P 128                // persistent blocks for recurrence

typedef unsigned long long ull;

// packed f32x2 helpers (FFMA2: only reachable via PTX fma.rn.f32x2)
__device__ __forceinline__ ull pk2(float lo, float hi) {
    ull r;
    asm("mov.b64 %0, {%1, %2};" : "=l"(r) : "r"(__float_as_uint(lo)), "r"(__float_as_uint(hi)));
    return r;
}
__device__ __forceinline__ void upk2(float& lo, float& hi, ull v) {
    uint32_t a, b;
    asm("mov.b64 {%0, %1}, %2;" : "=r"(a), "=r"(b) : "l"(v));
    lo = __uint_as_float(a); hi = __uint_as_float(b);
}
__device__ __forceinline__ ull fma2(ull a, ull b, ull c) {
    ull d;
    asm("fma.rn.f32x2 %0, %1, %2, %3;" : "=l"(d) : "l"(a), "l"(b), "l"(c));
    return d;
}

// ===========================================================================
// Persistent device state
// ===========================================================================
__device__ float g_hbuf[2][BH];          // double-buffered hidden state
__device__ unsigned g_count;             // monotonic barrier counter

__global__ void init_h_kernel(const float* __restrict__ h0) {
    int idx = blockIdx.x * blockDim.x + threadIdx.x;
    if (idx < BH) g_hbuf[0][idx] = h0[idx];
    if (idx == 0) g_count = 0u;
}

// ===========================================================================
// Input projection: out[m][n] = sum_i x[m][i]*Wih[n][i] + bih[n] + bhh[n]
// M=32768, N=1024, K=1024. BM=BN=128, BK=16, 8x8 thread tile, 256 threads.
// Inner product in packed fma.rn.f32x2. No min-blocks cap -> no spills.
// ===========================================================================
__global__ __launch_bounds__(256) void input_gemm_kernel(
    const float* __restrict__ x, const float* __restrict__ Wih,
    const float* __restrict__ bih, const float* __restrict__ bhh,
    float* __restrict__ out)
{
    __shared__ __align__(16) float As[16][132];
    __shared__ __align__(16) float Bs[16][132];

    const int tid = threadIdx.x;
    const int m0 = blockIdx.y * 128;
    const int n0 = blockIdx.x * 128;
    const int tx = tid & 15;   // -> n
    const int ty = tid >> 4;   // -> m

    ull acc2[8][4];
    #pragma unroll
    for (int i = 0; i < 8; i++)
        #pragma unroll
        for (int j = 0; j < 4; j++) acc2[i][j] = 0ull;

    for (int k0 = 0; k0 < D_IN; k0 += 16) {
        #pragma unroll
        for (int l = 0; l < 2; l++) {
            int f = tid + l * 256;
            int r = f >> 2, c = (f & 3) * 4;
            float4 v = *(const float4*)(x + (size_t)(m0 + r) * D_IN + k0 + c);
            As[c + 0][r] = v.x; As[c + 1][r] = v.y;
            As[c + 2][r] = v.z; As[c + 3][r] = v.w;
        }
        #pragma unroll
        for (int l = 0; l < 2; l++) {
            int f = tid + l * 256;
            int r = f >> 2, c = (f & 3) * 4;
            float4 v = *(const float4*)(Wih + (size_t)(n0 + r) * D_IN + k0 + c);
            Bs[c + 0][r] = v.x; Bs[c + 1][r] = v.y;
            Bs[c + 2][r] = v.z; Bs[c + 3][r] = v.w;
        }
        __syncthreads();
        #pragma unroll
        for (int k = 0; k < 16; k++) {
            float a[8], b[8];
            *(float4*)&a[0] = *(const float4*)&As[k][ty * 8];
            *(float4*)&a[4] = *(const float4*)&As[k][ty * 8 + 4];
            *(float4*)&b[0] = *(const float4*)&Bs[k][tx * 8];
            *(float4*)&b[4] = *(const float4*)&Bs[k][tx * 8 + 4];
            ull b2[4];
            #pragma unroll
            for (int q = 0; q < 4; q++) b2[q] = pk2(b[2 * q], b[2 * q + 1]);
            #pragma unroll
            for (int i = 0; i < 8; i++) {
                ull a2 = pk2(a[i], a[i]);
                #pragma unroll
                for (int q = 0; q < 4; q++)
                    acc2[i][q] = fma2(a2, b2[q], acc2[i][q]);
            }
        }
        __syncthreads();
    }

    // Epilogue: fused bias (b_ih + b_hh), vectorized stores
    #pragma unroll
    for (int i = 0; i < 8; i++) {
        int m = m0 + ty * 8 + i;
        float accf[8];
        #pragma unroll
        for (int q = 0; q < 4; q++) upk2(accf[2 * q], accf[2 * q + 1], acc2[i][q]);
        #pragma unroll
        for (int j = 0; j < 8; j += 4) {
            int n = n0 + tx * 8 + j;
            float4 o;
            o.x = accf[j + 0] + bih[n + 0] + bhh[n + 0];
            o.y = accf[j + 1] + bih[n + 1] + bhh[n + 1];
            o.z = accf[j + 2] + bih[n + 2] + bhh[n + 2];
            o.w = accf[j + 3] + bih[n + 3] + bhh[n + 3];
            *(float4*)(out + (size_t)m * D_H + n) = o;
        }
    }
}

// ===========================================================================
// Persistent recurrence: 512 steps, 128 blocks x 512 threads, fma.rn.f32x2.
// Block bx owns cols j0=bx*8. Thread: b = tid>>3 (batch), kc = tid&7 (K chunk
// of 128). Whh slice in smem as packed column-pairs, skewed every 128 k.
// Barrier: single monotonic counter (1 atomic + 1 poller per block).
// ===========================================================================
__global__ __launch_bounds__(512, 1) void rnn_persistent_kernel(
    const float* __restrict__ Whh, float* __restrict__ out, int write_tail)
{
    __shared__ __align__(16) ull Ws2[4096 + 16];

    const int tid = threadIdx.x;
    const int bx  = blockIdx.x;
    const int j0  = bx * 8;

    // One-time Whh slice load: Ws2[k*4 + (k>>7)*2 + jp] = (W[j0+2jp][k], W[j0+2jp+1][k])
    {
        const int k = tid * 2;
        #pragma unroll
        for (int jp = 0; jp < 4; jp++) {
            float2 wa = *(const float2*)(Whh + (size_t)(j0 + 2 * jp) * D_H + k);
            float2 wb = *(const float2*)(Whh + (size_t)(j0 + 2 * jp + 1) * D_H + k);
            Ws2[(size_t)k * 4 + ((k >> 7) << 1) + jp]             = pk2(wa.x, wb.x);
            Ws2[(size_t)(k + 1) * 4 + (((k + 1) >> 7) << 1) + jp] = pk2(wa.y, wb.y);
        }
    }
    __syncthreads();

    const int b  = tid >> 3;         // 0..63
    const int kc = tid & 7;          // 0..7
    const int kbase = kc << 7;       // kc * 128
    const ull* wbase = Ws2 + (kc << 1);   // fold the skew (k>>7 == kc in chunk)
    const int idx = b * D_H + j0 + kc;

    for (int t = 0; t < SEQ; t++) {
        const float* hrow = g_hbuf[t & 1] + b * D_H + kbase;
        float* hnew = g_hbuf[(t + 1) & 1];
        float* op = out + (size_t)t * BH + idx;

        // prefetch xproj early: hides DRAM latency off the critical path
        float xp = __ldcg(op);

        ull a0 = 0ull, a1 = 0ull, a2 = 0ull, a3 = 0ull;

        #pragma unroll 4
        for (int i = 0; i < 128; i += 8) {
            float hreg[8];
            float4 h0 = __ldcg((const float4*)(hrow + i));
            float4 h1 = __ldcg((const float4*)(hrow + i + 4));
            *(float4*)&hreg[0] = h0;
            *(float4*)&hreg[4] = h1;
            #pragma unroll
            for (int u = 0; u < 8; u++) {
                const ull* wp = wbase + ((size_t)(kbase + i + u) << 2);
                ulonglong2 wA = *(const ulonglong2*)(wp);
                ulonglong2 wB = *(const ulonglong2*)(wp + 2);
                ull hk2 = pk2(hreg[u], hreg[u]);
                a0 = fma2(hk2, wA.x, a0);
                a1 = fma2(hk2, wA.y, a1);
                a2 = fma2(hk2, wB.x, a2);
                a3 = fma2(hk2, wB.y, a3);
            }
        }

        float a[8];
        upk2(a[0], a[1], a0); upk2(a[2], a[3], a1);
        upk2(a[4], a[5], a2); upk2(a[6], a[7], a3);

        #pragma unroll
        for (int j = 0; j < 8; j++) {
            a[j] += __shfl_xor_sync(0xffffffffu, a[j], 1);
            a[j] += __shfl_xor_sync(0xffffffffu, a[j], 2);
            a[j] += __shfl_xor_sync(0xffffffffu, a[j], 4);
        }

        float s;
        switch (kc) {
            case 0: s = a[0]; break; case 1: s = a[1]; break;
            case 2: s = a[2]; break; case 3: s = a[3]; break;
            case 4: s = a[4]; break; case 5: s = a[5]; break;
            case 6: s = a[6]; break; default: s = a[7]; break;
        }

        float hv = tanhf(xp + s);
        *op = hv;
        __stcg(hnew + idx, hv);
        if (write_tail && t == SEQ - 1) out[(size_t)SEQ * BH + idx] = hv;

        // grid barrier: monotonic counter, 1 atomic + 1 poller per block
        if (t < SEQ - 1) {
            __threadfence();
            __syncthreads();
            if (tid == 0) {
                const unsigned target = (unsigned)(t + 1) * GRID_P;
                atomicAdd(&g_count, 1u);
                while (*((volatile unsigned*)&g_count) < target) { }
            }
            __syncthreads();
        }
    }
}

// ===========================================================================
extern "C" void kernel_launch(void* const* d_in, const int* in_sizes, int n_in,
                              void* d_out, int out_size) {
    const float* x   = (const float*)d_in[0];
    const float* h0  = (const float*)d_in[1];
    const float* Wih = (const float*)d_in[2];
    const float* bih = (const float*)d_in[3];
    const float* Whh = (const float*)d_in[4];
    const float* bhh = (const float*)d_in[5];
    float* out = (float*)d_out;

    init_h_kernel<<<(BH + 255) / 256, 256>>>(h0);

    input_gemm_kernel<<<dim3(D_H / 128, M_IN / 128), 256>>>(x, Wih, bih, bhh, out);

    long long total = (long long)SEQ * BH;
    int write_tail = ((long long)out_size >= total + BH) ? 1 : 0;
    rnn_persistent_kernel<<<GRID_P, 512>>>(Whh, out, write_tail);
}

// round 9
// speedup vs baseline: 1.3207x; 1.0229x over previous
#include <cuda_runtime.h>
#include <cuda_bf16.h>
#include <math.h>
#include <stdint.h>

#define SEQ    512
#define BATCH  64
#define D_IN   1024
#define D_H    1024
#define M_IN   (SEQ * BATCH)      // 32768
#define BH     (BATCH * D_H)      // 65536
#define GRID_P 128                // persistent blocks for recurrence

typedef unsigned long long ull;

// packed f32x2 helpers (FFMA2: only reachable via PTX fma.rn.f32x2)
__device__ __forceinline__ ull pk2(float lo, float hi) {
    ull r;
    asm("mov.b64 %0, {%1, %2};" : "=l"(r) : "r"(__float_as_uint(lo)), "r"(__float_as_uint(hi)));
    return r;
}
__device__ __forceinline__ void upk2(float& lo, float& hi, ull v) {
    uint32_t a, b;
    asm("mov.b64 {%0, %1}, %2;" : "=r"(a), "=r"(b) : "l"(v));
    lo = __uint_as_float(a); hi = __uint_as_float(b);
}
__device__ __forceinline__ ull fma2(ull a, ull b, ull c) {
    ull d;
    asm("fma.rn.f32x2 %0, %1, %2, %3;" : "=l"(d) : "l"(a), "l"(b), "l"(c));
    return d;
}

// ===========================================================================
// Persistent device state: barrier counter. Reset to 0 by the GEMM kernel
// (stream-ordered before the rnn kernel), so every run uses absolute targets.
// ===========================================================================
__device__ unsigned g_count;

// ===========================================================================
// Input projection: out[m][n] = sum_i x[m][i]*Wih[n][i] + bih[n] + bhh[n]
// M=32768, N=1024, K=1024. BM=BN=128, BK=16, 8x8 thread tile, 256 threads.
// Inner product in packed fma.rn.f32x2. (R5-proven body.)
// Block (0,0) also resets the rnn barrier counter.
// ===========================================================================
__global__ __launch_bounds__(256) void input_gemm_kernel(
    const float* __restrict__ x, const float* __restrict__ Wih,
    const float* __restrict__ bih, const float* __restrict__ bhh,
    float* __restrict__ out)
{
    __shared__ __align__(16) float As[16][132];
    __shared__ __align__(16) float Bs[16][132];

    const int tid = threadIdx.x;
    if (blockIdx.x == 0 && blockIdx.y == 0 && tid == 0) g_count = 0u;

    const int m0 = blockIdx.y * 128;
    const int n0 = blockIdx.x * 128;
    const int tx = tid & 15;   // -> n
    const int ty = tid >> 4;   // -> m

    ull acc2[8][4];
    #pragma unroll
    for (int i = 0; i < 8; i++)
        #pragma unroll
        for (int j = 0; j < 4; j++) acc2[i][j] = 0ull;

    for (int k0 = 0; k0 < D_IN; k0 += 16) {
        #pragma unroll
        for (int l = 0; l < 2; l++) {
            int f = tid + l * 256;
            int r = f >> 2, c = (f & 3) * 4;
            float4 v = *(const float4*)(x + (size_t)(m0 + r) * D_IN + k0 + c);
            As[c + 0][r] = v.x; As[c + 1][r] = v.y;
            As[c + 2][r] = v.z; As[c + 3][r] = v.w;
        }
        #pragma unroll
        for (int l = 0; l < 2; l++) {
            int f = tid + l * 256;
            int r = f >> 2, c = (f & 3) * 4;
            float4 v = *(const float4*)(Wih + (size_t)(n0 + r) * D_IN + k0 + c);
            Bs[c + 0][r] = v.x; Bs[c + 1][r] = v.y;
            Bs[c + 2][r] = v.z; Bs[c + 3][r] = v.w;
        }
        __syncthreads();
        #pragma unroll
        for (int k = 0; k < 16; k++) {
            float a[8], b[8];
            *(float4*)&a[0] = *(const float4*)&As[k][ty * 8];
            *(float4*)&a[4] = *(const float4*)&As[k][ty * 8 + 4];
            *(float4*)&b[0] = *(const float4*)&Bs[k][tx * 8];
            *(float4*)&b[4] = *(const float4*)&Bs[k][tx * 8 + 4];
            ull b2[4];
            #pragma unroll
            for (int q = 0; q < 4; q++) b2[q] = pk2(b[2 * q], b[2 * q + 1]);
            #pragma unroll
            for (int i = 0; i < 8; i++) {
                ull a2 = pk2(a[i], a[i]);
                #pragma unroll
                for (int q = 0; q < 4; q++)
                    acc2[i][q] = fma2(a2, b2[q], acc2[i][q]);
            }
        }
        __syncthreads();
    }

    // Epilogue: fused bias (b_ih + b_hh), vectorized stores
    #pragma unroll
    for (int i = 0; i < 8; i++) {
        int m = m0 + ty * 8 + i;
        float accf[8];
        #pragma unroll
        for (int q = 0; q < 4; q++) upk2(accf[2 * q], accf[2 * q + 1], acc2[i][q]);
        #pragma unroll
        for (int j = 0; j < 8; j += 4) {
            int n = n0 + tx * 8 + j;
            float4 o;
            o.x = accf[j + 0] + bih[n + 0] + bhh[n + 0];
            o.y = accf[j + 1] + bih[n + 1] + bhh[n + 1];
            o.z = accf[j + 2] + bih[n + 2] + bhh[n + 2];
            o.w = accf[j + 3] + bih[n + 3] + bhh[n + 3];
            *(float4*)(out + (size_t)m * D_H + n) = o;
        }
    }
}

// ===========================================================================
// Persistent recurrence: 512 steps, 128 blocks x 512 threads, fma.rn.f32x2.
// h state lives in the out buffer: step t reads out[t-1] (t=0: h0).
// Barrier: R5-proven absolute-target atomic counter (reset by gemm kernel).
// ===========================================================================
__global__ __launch_bounds__(512, 1) void rnn_persistent_kernel(
    const float* __restrict__ h0, const float* __restrict__ Whh,
    float* __restrict__ out, int write_tail)
{
    __shared__ __align__(16) ull Ws2[4096 + 16];

    const int tid = threadIdx.x;
    const int bx  = blockIdx.x;
    const int j0  = bx * 8;

    // One-time Whh slice load: Ws2[k*4 + (k>>7)*2 + jp] = (W[j0+2jp][k], W[j0+2jp+1][k])
    {
        const int k = tid * 2;
        #pragma unroll
        for (int jp = 0; jp < 4; jp++) {
            float2 wa = *(const float2*)(Whh + (size_t)(j0 + 2 * jp) * D_H + k);
            float2 wb = *(const float2*)(Whh + (size_t)(j0 + 2 * jp + 1) * D_H + k);
            Ws2[(size_t)k * 4 + ((k >> 7) << 1) + jp]             = pk2(wa.x, wb.x);
            Ws2[(size_t)(k + 1) * 4 + (((k + 1) >> 7) << 1) + jp] = pk2(wa.y, wb.y);
        }
    }
    __syncthreads();

    const int b  = tid >> 3;         // 0..63
    const int kc = tid & 7;          // 0..7
    const int kbase = kc << 7;       // kc * 128
    const ull* wbase = Ws2 + (kc << 1);   // fold the skew (k>>7 == kc in chunk)
    const int idx = b * D_H + j0 + kc;

    for (int t = 0; t < SEQ; t++) {
        const float* hsrc = (t == 0) ? h0 : out + (size_t)(t - 1) * BH;
        const float* hrow = hsrc + b * D_H + kbase;
        float* op = out + (size_t)t * BH + idx;

        // prefetch xproj early: hides DRAM latency off the critical path
        float xp = __ldcg(op);

        ull a0 = 0ull, a1 = 0ull, a2 = 0ull, a3 = 0ull;

        #pragma unroll 4
        for (int i = 0; i < 128; i += 8) {
            float hreg[8];
            float4 hv0 = __ldcg((const float4*)(hrow + i));
            float4 hv1 = __ldcg((const float4*)(hrow + i + 4));
            *(float4*)&hreg[0] = hv0;
            *(float4*)&hreg[4] = hv1;
            #pragma unroll
            for (int u = 0; u < 8; u++) {
                const ull* wp = wbase + ((size_t)(kbase + i + u) << 2);
                ulonglong2 wA = *(const ulonglong2*)(wp);
                ulonglong2 wB = *(const ulonglong2*)(wp + 2);
                ull hk2 = pk2(hreg[u], hreg[u]);
                a0 = fma2(hk2, wA.x, a0);
                a1 = fma2(hk2, wA.y, a1);
                a2 = fma2(hk2, wB.x, a2);
                a3 = fma2(hk2, wB.y, a3);
            }
        }

        float a[8];
        upk2(a[0], a[1], a0); upk2(a[2], a[3], a1);
        upk2(a[4], a[5], a2); upk2(a[6], a[7], a3);

        #pragma unroll
        for (int j = 0; j < 8; j++) {
            a[j] += __shfl_xor_sync(0xffffffffu, a[j], 1);
            a[j] += __shfl_xor_sync(0xffffffffu, a[j], 2);
            a[j] += __shfl_xor_sync(0xffffffffu, a[j], 4);
        }

        float s;
        switch (kc) {
            case 0: s = a[0]; break; case 1: s = a[1]; break;
            case 2: s = a[2]; break; case 3: s = a[3]; break;
            case 4: s = a[4]; break; case 5: s = a[5]; break;
            case 6: s = a[6]; break; default: s = a[7]; break;
        }

        float hv = tanhf(xp + s);
        __stcg(op, hv);
        if (write_tail && t == SEQ - 1) __stcg(out + (size_t)SEQ * BH + idx, hv);

        // grid barrier: absolute target, 1 atomic + 1 volatile poller per block
        if (t < SEQ - 1) {
            __threadfence();
            __syncthreads();
            if (tid == 0) {
                const unsigned target = (unsigned)(t + 1) * GRID_P;
                atomicAdd(&g_count, 1u);
                while (*((volatile unsigned*)&g_count) < target) { }
            }
            __syncthreads();
        }
    }
}

// ===========================================================================
extern "C" void kernel_launch(void* const* d_in, const int* in_sizes, int n_in,
                              void* d_out, int out_size) {
    const float* x   = (const float*)d_in[0];
    const float* h0  = (const float*)d_in[1];
    const float* Wih = (const float*)d_in[2];
    const float* bih = (const float*)d_in[3];
    const float* Whh = (const float*)d_in[4];
    const float* bhh = (const float*)d_in[5];
    float* out = (float*)d_out;

    input_gemm_kernel<<<dim3(D_H / 128, M_IN / 128), 256>>>(x, Wih, bih, bhh, out);

    long long total = (long long)SEQ * BH;
    int write_tail = ((long long)out_size >= total + BH) ? 1 : 0;
    rnn_persistent_kernel<<<GRID_P, 512>>>(h0, Whh, out, write_tail);
}